// round 15
// baseline (speedup 1.0000x reference)
#include <cuda_runtime.h>
#include <cuda_fp16.h>
#include <cstdint>

#define NB 4
#define NT 2048
#define NC 1024
#define NH 16
#define ND 64
#define NM (NB*NT)           // 8192 rows

// Scratch (allocation-free)
__device__ __align__(16) uint32_t g_Xt[(size_t)NM*NC];       // x as tf32 bits
__device__ __align__(16) uint32_t g_Wqkvt[(size_t)NC*3*NC];  // Wqkv as tf32 bits, [k][n]
__device__ __align__(16) __half   g_Qh[(size_t)NB*NH*NT*ND]; // pre-scaled by 0.125
__device__ __align__(16) __half   g_Kh[(size_t)NB*NH*NT*ND];
__device__ __align__(16) __half   g_Vh[(size_t)NB*NH*NT*ND];
__device__ __align__(16) float    g_AO[(size_t)NM*NC];

// ===========================================================================
// helpers
// ===========================================================================
__device__ __forceinline__ uint32_t smem_to_u32(const void* p) {
    uint32_t a;
    asm("{ .reg .u64 t; cvta.to.shared.u64 t, %1; cvt.u32.u64 %0, t; }"
        : "=r"(a) : "l"(p));
    return a;
}
__device__ __forceinline__ uint32_t f2tf32(float f) {
    uint32_t r; asm("cvt.rna.tf32.f32 %0, %1;" : "=r"(r) : "f"(f)); return r;
}
__device__ __forceinline__ uint32_t h2pack(float lo, float hi) {
    uint32_t r;
    asm("cvt.rn.f16x2.f32 %0, %1, %2;" : "=r"(r) : "f"(hi), "f"(lo));
    return r;
}
__device__ __forceinline__ void mma_tf32(float* d, const uint32_t* a, const uint32_t* b) {
    asm volatile(
        "mma.sync.aligned.m16n8k8.row.col.f32.tf32.tf32.f32 "
        "{%0,%1,%2,%3}, {%4,%5,%6,%7}, {%8,%9}, {%0,%1,%2,%3};\n"
        : "+f"(d[0]), "+f"(d[1]), "+f"(d[2]), "+f"(d[3])
        : "r"(a[0]), "r"(a[1]), "r"(a[2]), "r"(a[3]), "r"(b[0]), "r"(b[1]));
}
__device__ __forceinline__ void mma_f16(float* d, const uint32_t* a, const uint32_t* b) {
    asm volatile(
        "mma.sync.aligned.m16n8k16.row.col.f32.f16.f16.f32 "
        "{%0,%1,%2,%3}, {%4,%5,%6,%7}, {%8,%9}, {%0,%1,%2,%3};\n"
        : "+f"(d[0]), "+f"(d[1]), "+f"(d[2]), "+f"(d[3])
        : "r"(a[0]), "r"(a[1]), "r"(a[2]), "r"(a[3]), "r"(b[0]), "r"(b[1]));
}
#define LDSM_X4(R0,R1,R2,R3,A) \
    asm volatile("ldmatrix.sync.aligned.m8n8.x4.shared.b16 {%0,%1,%2,%3}, [%4];" \
        : "=r"(R0),"=r"(R1),"=r"(R2),"=r"(R3) : "r"(A))
#define LDSM_X4_T(R0,R1,R2,R3,A) \
    asm volatile("ldmatrix.sync.aligned.m8n8.x4.trans.shared.b16 {%0,%1,%2,%3}, [%4];" \
        : "=r"(R0),"=r"(R1),"=r"(R2),"=r"(R3) : "r"(A))
#define CP_ASYNC16(dst, src) \
    asm volatile("cp.async.cg.shared.global [%0], [%1], 16;" \
        :: "r"(dst), "l"(src) : "memory")
#define CP_COMMIT() asm volatile("cp.async.commit_group;" ::: "memory")
#define CP_WAIT1()  asm volatile("cp.async.wait_group 1;" ::: "memory")
#define CP_WAIT0()  asm volatile("cp.async.wait_group 0;" ::: "memory")

// ===========================================================================
// Converters — scalar / grid-stride (proven trap-free pattern)
// ===========================================================================
__global__ __launch_bounds__(256) void conv_tf32_kernel(
    const float* __restrict__ src, uint32_t* __restrict__ dst, size_t n)
{
    for (size_t i = (size_t)blockIdx.x * blockDim.x + threadIdx.x; i < n;
         i += (size_t)gridDim.x * blockDim.x)
        dst[i] = f2tf32(src[i]);
}

// ===========================================================================
// tf32 mma GEMM (QKV) — R10-proven structure; fragment loads are now plain
// uint32 LDS (operands pre-converted to tf32 bits). cp.async byte-identical.
// Block 128x128, BK=16, 3-stage, 256 threads (8 warps 4x2), warp tile 32x64.
// ===========================================================================
#define GSTAGES 3
#define GEMM_SMEM (GSTAGES * 16384)

__global__ __launch_bounds__(256) void gemm_tc_qkv(
    const uint32_t* __restrict__ A, const uint32_t* __restrict__ B)
{
    extern __shared__ char smc[];
    const uint32_t sb = smem_to_u32(smc);
    const uint32_t* smu = (const uint32_t*)smc;
    constexpr int LDB = 3*NC;

    const int tid  = threadIdx.x;
    const int lane = tid & 31, wid = tid >> 5;
    const int wm = (wid & 3) * 32, wn = (wid >> 2) * 64;
    const int g = lane >> 2, q4 = lane & 3;
    const int rowA0 = blockIdx.y * 128, colB0 = blockIdx.x * 128;

    const int la_row = tid >> 2, la_k4 = (tid & 3) << 2;
    const int lb_k   = tid >> 5, lb_n4 = (tid & 31) << 2;

    float acc[2][8][4];
    #pragma unroll
    for (int i = 0; i < 2; i++)
        #pragma unroll
        for (int j = 0; j < 8; j++)
            #pragma unroll
            for (int k = 0; k < 4; k++) acc[i][j][k] = 0.f;

    constexpr int NIT = NC / 16;

    auto issue = [&](int s) {
        const uint32_t bufA = sb + (s % GSTAGES) * 16384;
        const uint32_t bufB = bufA + 8192;
        const int k0 = s * 16;
        #pragma unroll
        for (int r = 0; r < 2; r++) {
            int row = la_row + r*64;
            uint32_t d = bufA + row*64 + ((la_k4 ^ (((row>>1)&3)<<2)) << 2);
            CP_ASYNC16(d, &A[(size_t)(rowA0 + row) * NC + k0 + la_k4]);
        }
        #pragma unroll
        for (int r = 0; r < 2; r++) {
            int k = lb_k + r*8;
            uint32_t d = bufB + k*512 + ((lb_n4 ^ ((k&3)<<3)) << 2);
            CP_ASYNC16(d, &B[(size_t)(k0 + k) * LDB + colB0 + lb_n4]);
        }
        CP_COMMIT();
    };

    issue(0);
    issue(1);

    for (int s = 0; s < NIT; s++) {
        if (s + 2 < NIT) CP_WAIT1(); else CP_WAIT0();
        __syncthreads();
        if (s + 2 < NIT) issue(s + 2);

        const uint32_t* bufA = smu + (s % GSTAGES) * 4096;
        const uint32_t* bufB = bufA + 2048;

        #pragma unroll
        for (int kk = 0; kk < 2; kk++) {
            const int kb = kk * 8;
            uint32_t a[2][4];
            #pragma unroll
            for (int i = 0; i < 2; i++) {
                int row = wm + i*16 + g;
                int sw = ((row >> 1) & 3) << 2;
                a[i][0] = bufA[ row     *16 + ((kb + q4    ) ^ sw)];
                a[i][1] = bufA[(row + 8)*16 + ((kb + q4    ) ^ sw)];
                a[i][2] = bufA[ row     *16 + ((kb + q4 + 4) ^ sw)];
                a[i][3] = bufA[(row + 8)*16 + ((kb + q4 + 4) ^ sw)];
            }
            const int swb = q4 << 3;
            #pragma unroll
            for (int j = 0; j < 8; j++) {
                int n = wn + j*8 + g;
                uint32_t b2[2];
                b2[0] = bufB[(kb + q4    )*128 + (n ^ swb)];
                b2[1] = bufB[(kb + q4 + 4)*128 + (n ^ swb)];
                mma_tf32(acc[0][j], a[0], b2);
                mma_tf32(acc[1][j], a[1], b2);
            }
        }
    }

    // scatter epilogue -> f16 Q/K/V (proven)
    #pragma unroll
    for (int i = 0; i < 2; i++) {
        #pragma unroll
        for (int j = 0; j < 8; j++) {
            #pragma unroll
            for (int half = 0; half < 2; half++) {
                int row = rowA0 + wm + i*16 + g + half*8;
                int col = colB0 + wn + j*8 + 2*q4;
                int which = col >> 10, h = (col >> 6) & 15, d = col & 63;
                int bb = row >> 11, t = row & (NT - 1);
                __half* dst = (which == 0) ? g_Qh : (which == 1) ? g_Kh : g_Vh;
                float sc = (which == 0) ? 0.125f : 1.0f;
                *(uint32_t*)&dst[(((size_t)(bb*NH + h) * NT + t) << 6) + d] =
                    h2pack(acc[i][j][half*2] * sc, acc[i][j][half*2+1] * sc);
            }
        }
    }
}

// ===========================================================================
// PROVEN tf32 mma.sync GEMM (out-projection). Reads fp32 g_AO + fp32 Wout.
// ===========================================================================
__global__ __launch_bounds__(256) void gemm_tc_out(
    const float* __restrict__ B, float* __restrict__ C)
{
    extern __shared__ float smf[];
    const uint32_t sb = smem_to_u32(smf);
    const float* __restrict__ A = g_AO;
    constexpr int LDB = NC;

    const int tid  = threadIdx.x;
    const int lane = tid & 31, wid = tid >> 5;
    const int wm = (wid & 3) * 32, wn = (wid >> 2) * 64;
    const int g = lane >> 2, q4 = lane & 3;
    const int rowA0 = blockIdx.y * 128, colB0 = blockIdx.x * 128;

    const int la_row = tid >> 2, la_k4 = (tid & 3) << 2;
    const int lb_k   = tid >> 5, lb_n4 = (tid & 31) << 2;

    float acc[2][8][4];
    #pragma unroll
    for (int i = 0; i < 2; i++)
        #pragma unroll
        for (int j = 0; j < 8; j++)
            #pragma unroll
            for (int k = 0; k < 4; k++) acc[i][j][k] = 0.f;

    constexpr int NIT = NC / 16;

    auto issue = [&](int s) {
        const uint32_t bufA = sb + (s % GSTAGES) * 16384;
        const uint32_t bufB = bufA + 8192;
        const int k0 = s * 16;
        #pragma unroll
        for (int r = 0; r < 2; r++) {
            int row = la_row + r*64;
            uint32_t d = bufA + row*64 + ((la_k4 ^ (((row>>1)&3)<<2)) << 2);
            CP_ASYNC16(d, &A[(size_t)(rowA0 + row) * NC + k0 + la_k4]);
        }
        #pragma unroll
        for (int r = 0; r < 2; r++) {
            int k = lb_k + r*8;
            uint32_t d = bufB + k*512 + ((lb_n4 ^ ((k&3)<<3)) << 2);
            CP_ASYNC16(d, &B[(size_t)(k0 + k) * LDB + colB0 + lb_n4]);
        }
        CP_COMMIT();
    };

    issue(0);
    issue(1);

    for (int s = 0; s < NIT; s++) {
        if (s + 2 < NIT) CP_WAIT1(); else CP_WAIT0();
        __syncthreads();
        if (s + 2 < NIT) issue(s + 2);

        const float* bufA = smf + (s % GSTAGES) * 4096;
        const float* bufB = bufA + 2048;

        #pragma unroll
        for (int kk = 0; kk < 2; kk++) {
            const int kb = kk * 8;
            uint32_t a[2][4];
            #pragma unroll
            for (int i = 0; i < 2; i++) {
                int row = wm + i*16 + g;
                int sw = ((row >> 1) & 3) << 2;
                a[i][0] = f2tf32(bufA[ row     *16 + ((kb + q4    ) ^ sw)]);
                a[i][1] = f2tf32(bufA[(row + 8)*16 + ((kb + q4    ) ^ sw)]);
                a[i][2] = f2tf32(bufA[ row     *16 + ((kb + q4 + 4) ^ sw)]);
                a[i][3] = f2tf32(bufA[(row + 8)*16 + ((kb + q4 + 4) ^ sw)]);
            }
            const int swb = q4 << 3;
            #pragma unroll
            for (int j = 0; j < 8; j++) {
                int n = wn + j*8 + g;
                uint32_t b2[2];
                b2[0] = f2tf32(bufB[(kb + q4    )*128 + (n ^ swb)]);
                b2[1] = f2tf32(bufB[(kb + q4 + 4)*128 + (n ^ swb)]);
                mma_tf32(acc[0][j], a[0], b2);
                mma_tf32(acc[1][j], a[1], b2);
            }
        }
    }

    #pragma unroll
    for (int i = 0; i < 2; i++) {
        #pragma unroll
        for (int j = 0; j < 8; j++) {
            #pragma unroll
            for (int half = 0; half < 2; half++) {
                int row = rowA0 + wm + i*16 + g + half*8;
                int col = colB0 + wn + j*8 + 2*q4;
                *(float2*)&C[(size_t)row * NC + col] =
                    make_float2(acc[i][j][half*2], acc[i][j][half*2+1]);
            }
        }
    }
}

// ===========================================================================
// PROVEN fp16 flash attention (fp32 g_AO output). VERBATIM R10/R14.
// ===========================================================================
#define ATTN_SMEM (8192 + 2*16384)
#define SWC(c, lg) ((uint32_t)(((c) ^ (lg)) << 4))

__global__ __launch_bounds__(128) void attn_f16()
{
    extern __shared__ char smc[];
    const uint32_t sb = smem_to_u32(smc);

    const int tid = threadIdx.x;
    const int lane = tid & 31, w = tid >> 5;
    const int g = lane >> 2, q4 = lane & 3;
    const int lg = lane & 7, l8 = (lane >> 3) & 1, l16 = lane >> 4;
    const int qt = blockIdx.x, bh = blockIdx.y;
    const int b = bh >> 4, h = bh & 15;
    const int q0 = qt * 64;

    const __half* Qg  = g_Qh + ((size_t)bh * NT + q0) * ND;
    const __half* Kg0 = g_Kh + (size_t)bh * NT * ND;
    const __half* Vg0 = g_Vh + (size_t)bh * NT * ND;

    const int ld_row = tid >> 3, ld_c = tid & 7;

    #pragma unroll
    for (int r = 0; r < 4; r++) {
        int row = ld_row + r * 16;
        CP_ASYNC16(sb + row*128 + SWC(ld_c, row & 7), &Qg[row*ND + ld_c*8]);
    }
    CP_COMMIT();
    CP_WAIT0();
    __syncthreads();

    uint32_t qf[4][4];
    {
        uint32_t qRow = sb + (w*16 + lg + l8*8) * 128;
        #pragma unroll
        for (int kc = 0; kc < 4; kc++)
            LDSM_X4(qf[kc][0], qf[kc][1], qf[kc][2], qf[kc][3],
                    qRow + SWC(2*kc + l16, lg));
    }
    __syncthreads();

    uint32_t kRow[4], vRow[4];
    #pragma unroll
    for (int ng = 0; ng < 4; ng++) kRow[ng] = (ng*16 + lg + l16*8) * 128;
    #pragma unroll
    for (int kc = 0; kc < 4; kc++) vRow[kc] = (kc*16 + lg + l8*8) * 128;

    auto issueKV = [&](int jt) {
        const uint32_t kb = sb + 8192 + (jt & 1) * 16384;
        const uint32_t vb = kb + 8192;
        const __half* Kg = Kg0 + (size_t)jt*64*ND;
        const __half* Vg = Vg0 + (size_t)jt*64*ND;
        #pragma unroll
        for (int r = 0; r < 4; r++) {
            int row = ld_row + r * 16;
            uint32_t swo = row*128 + SWC(ld_c, row & 7);
            CP_ASYNC16(kb + swo, &Kg[row*ND + ld_c*8]);
            CP_ASYNC16(vb + swo, &Vg[row*ND + ld_c*8]);
        }
        CP_COMMIT();
    };

    float o[8][4];
    #pragma unroll
    for (int i = 0; i < 8; i++)
        #pragma unroll
        for (int j = 0; j < 4; j++) o[i][j] = 0.f;
    float m0 = -1e30f, m1 = -1e30f, l0 = 0.f, l1 = 0.f;

    issueKV(0);

    for (int jt = 0; jt <= qt; jt++) {
        __syncthreads();
        if (jt + 1 <= qt) { issueKV(jt + 1); CP_WAIT1(); }
        else              { CP_WAIT0(); }
        __syncthreads();

        const uint32_t kb = sb + 8192 + (jt & 1) * 16384;
        const uint32_t vb = kb + 8192;

        float s[8][4];
        #pragma unroll
        for (int i = 0; i < 8; i++)
            #pragma unroll
            for (int j = 0; j < 4; j++) s[i][j] = 0.f;
        #pragma unroll
        for (int kc = 0; kc < 4; kc++) {
            #pragma unroll
            for (int ng = 0; ng < 4; ng++) {
                uint32_t b0, b1, b2, b3;
                LDSM_X4(b0, b1, b2, b3, kb + kRow[ng] + SWC(2*kc + l8, lg));
                uint32_t bl[2] = {b0, b1}, bhh[2] = {b2, b3};
                mma_f16(s[2*ng],   qf[kc], bl);
                mma_f16(s[2*ng+1], qf[kc], bhh);
            }
        }

        if (jt == qt) {
            int r0 = w*16 + g, r1 = r0 + 8;
            #pragma unroll
            for (int nf = 0; nf < 8; nf++) {
                int c = nf*8 + 2*q4;
                if (c     > r0) s[nf][0] = -1e30f;
                if (c + 1 > r0) s[nf][1] = -1e30f;
                if (c     > r1) s[nf][2] = -1e30f;
                if (c + 1 > r1) s[nf][3] = -1e30f;
            }
        }

        float mx0 = -1e30f, mx1 = -1e30f;
        #pragma unroll
        for (int nf = 0; nf < 8; nf++) {
            mx0 = fmaxf(mx0, fmaxf(s[nf][0], s[nf][1]));
            mx1 = fmaxf(mx1, fmaxf(s[nf][2], s[nf][3]));
        }
        mx0 = fmaxf(mx0, __shfl_xor_sync(0xffffffffu, mx0, 1));
        mx0 = fmaxf(mx0, __shfl_xor_sync(0xffffffffu, mx0, 2));
        mx1 = fmaxf(mx1, __shfl_xor_sync(0xffffffffu, mx1, 1));
        mx1 = fmaxf(mx1, __shfl_xor_sync(0xffffffffu, mx1, 2));
        float nm0 = fmaxf(m0, mx0), nm1 = fmaxf(m1, mx1);
        float c0 = __expf(m0 - nm0), c1 = __expf(m1 - nm1);
        m0 = nm0; m1 = nm1;
        float ps0 = 0.f, ps1 = 0.f;
        #pragma unroll
        for (int nf = 0; nf < 8; nf++) {
            s[nf][0] = __expf(s[nf][0] - nm0);
            s[nf][1] = __expf(s[nf][1] - nm0);
            s[nf][2] = __expf(s[nf][2] - nm1);
            s[nf][3] = __expf(s[nf][3] - nm1);
            ps0 += s[nf][0] + s[nf][1];
            ps1 += s[nf][2] + s[nf][3];
        }
        ps0 += __shfl_xor_sync(0xffffffffu, ps0, 1);
        ps0 += __shfl_xor_sync(0xffffffffu, ps0, 2);
        ps1 += __shfl_xor_sync(0xffffffffu, ps1, 1);
        ps1 += __shfl_xor_sync(0xffffffffu, ps1, 2);
        l0 = l0 * c0 + ps0;
        l1 = l1 * c1 + ps1;
        #pragma unroll
        for (int df = 0; df < 8; df++) {
            o[df][0] *= c0; o[df][1] *= c0;
            o[df][2] *= c1; o[df][3] *= c1;
        }

        uint32_t p[4][4];
        #pragma unroll
        for (int kc = 0; kc < 4; kc++) {
            p[kc][0] = h2pack(s[2*kc][0],   s[2*kc][1]);
            p[kc][1] = h2pack(s[2*kc][2],   s[2*kc][3]);
            p[kc][2] = h2pack(s[2*kc+1][0], s[2*kc+1][1]);
            p[kc][3] = h2pack(s[2*kc+1][2], s[2*kc+1][3]);
        }

        #pragma unroll
        for (int kc = 0; kc < 4; kc++) {
            #pragma unroll
            for (int dg = 0; dg < 4; dg++) {
                uint32_t v0, v1, v2, v3;
                LDSM_X4_T(v0, v1, v2, v3, vb + vRow[kc] + SWC(2*dg + l16, lg));
                uint32_t bl[2] = {v0, v1}, bhh[2] = {v2, v3};
                mma_f16(o[2*dg],   p[kc], bl);
                mma_f16(o[2*dg+1], p[kc], bhh);
            }
        }
    }

    float i0 = 1.f / l0, i1 = 1.f / l1;
    int r0 = q0 + w*16 + g;
    #pragma unroll
    for (int df = 0; df < 8; df++) {
        int col = h*ND + df*8 + 2*q4;
        *(float2*)&g_AO[(size_t)(b*NT + r0) * NC + col] =
            make_float2(o[df][0]*i0, o[df][1]*i0);
        *(float2*)&g_AO[(size_t)(b*NT + r0 + 8) * NC + col] =
            make_float2(o[df][2]*i1, o[df][3]*i1);
    }
}

// ---------------------------------------------------------------------------
extern "C" void kernel_launch(void* const* d_in, const int* in_sizes, int n_in,
                              void* d_out, int out_size)
{
    const float* x    = (const float*)d_in[0];
    const float* Wqkv = (const float*)d_in[1];
    const float* Wout = (const float*)d_in[2];
    // mask is deterministic tril -> hard-coded causal
    float* out = (float*)d_out;

    cudaFuncSetAttribute(gemm_tc_qkv,
                         cudaFuncAttributeMaxDynamicSharedMemorySize, GEMM_SMEM);
    cudaFuncSetAttribute(gemm_tc_out,
                         cudaFuncAttributeMaxDynamicSharedMemorySize, GEMM_SMEM);
    cudaFuncSetAttribute(attn_f16,
                         cudaFuncAttributeMaxDynamicSharedMemorySize, ATTN_SMEM);

    // pre-convert operands to tf32 bit patterns (scalar, grid-stride)
    conv_tf32_kernel<<<2048, 256>>>(x, g_Xt, (size_t)NM * NC);
    conv_tf32_kernel<<<2048, 256>>>(Wqkv, g_Wqkvt, (size_t)NC * 3*NC);

    dim3 g1(3*NC / 128, NM / 128);   // 24 x 64
    gemm_tc_qkv<<<g1, 256, GEMM_SMEM>>>(g_Xt, g_Wqkvt);

    dim3 ga(NT / 64, NB * NH);       // 32 x 64
    attn_f16<<<ga, 128, ATTN_SMEM>>>();

    dim3 g2(NC / 128, NM / 128);     // 8 x 64
    gemm_tc_out<<<g2, 256, GEMM_SMEM>>>(Wout, out);
}

// round 16
// speedup vs baseline: 33.0616x; 33.0616x over previous
#include <cuda_runtime.h>
#include <cuda_fp16.h>
#include <cstdint>

#define NB 4
#define NT 2048
#define NC 1024
#define NH 16
#define ND 64
#define NM (NB*NT)           // 8192 rows

// Scratch — referenced ONLY inside device code (never passed as kernel args:
// host-side symbol decay yields the HOST shadow address, which ATS happily
// services over NVLink-C2C at ~200GB/s — the root cause of R7-R15 anomalies).
__device__ __align__(16) __half g_Xh[(size_t)NM*NC];
__device__ __align__(16) __half g_WqkvT[(size_t)3*NC*NC];   // [n=3072][k=1024]
__device__ __align__(16) __half g_WoutT[(size_t)NC*NC];     // [n=1024][k=1024]
__device__ __align__(16) __half g_Qh[(size_t)NB*NH*NT*ND];  // pre-scaled by 0.125
__device__ __align__(16) __half g_Kh[(size_t)NB*NH*NT*ND];
__device__ __align__(16) __half g_Vh[(size_t)NB*NH*NT*ND];
__device__ __align__(16) __half g_AOh[(size_t)NM*NC];

// ===========================================================================
// helpers
// ===========================================================================
__device__ __forceinline__ uint32_t smem_to_u32(const void* p) {
    uint32_t a;
    asm("{ .reg .u64 t; cvta.to.shared.u64 t, %1; cvt.u32.u64 %0, t; }"
        : "=r"(a) : "l"(p));
    return a;
}
__device__ __forceinline__ uint32_t h2pack(float lo, float hi) {
    uint32_t r;
    asm("cvt.rn.f16x2.f32 %0, %1, %2;" : "=r"(r) : "f"(hi), "f"(lo));
    return r;
}
__device__ __forceinline__ void mma_f16(float* d, const uint32_t* a, const uint32_t* b) {
    asm volatile(
        "mma.sync.aligned.m16n8k16.row.col.f32.f16.f16.f32 "
        "{%0,%1,%2,%3}, {%4,%5,%6,%7}, {%8,%9}, {%0,%1,%2,%3};\n"
        : "+f"(d[0]), "+f"(d[1]), "+f"(d[2]), "+f"(d[3])
        : "r"(a[0]), "r"(a[1]), "r"(a[2]), "r"(a[3]), "r"(b[0]), "r"(b[1]));
}
#define LDSM_X4(R0,R1,R2,R3,A) \
    asm volatile("ldmatrix.sync.aligned.m8n8.x4.shared.b16 {%0,%1,%2,%3}, [%4];" \
        : "=r"(R0),"=r"(R1),"=r"(R2),"=r"(R3) : "r"(A))
#define LDSM_X4_T(R0,R1,R2,R3,A) \
    asm volatile("ldmatrix.sync.aligned.m8n8.x4.trans.shared.b16 {%0,%1,%2,%3}, [%4];" \
        : "=r"(R0),"=r"(R1),"=r"(R2),"=r"(R3) : "r"(A))
#define CP_ASYNC16(dst, src) \
    asm volatile("cp.async.cg.shared.global [%0], [%1], 16;" \
        :: "r"(dst), "l"(src) : "memory")
#define CP_COMMIT() asm volatile("cp.async.commit_group;" ::: "memory")
#define CP_WAIT1()  asm volatile("cp.async.wait_group 1;" ::: "memory")
#define CP_WAIT0()  asm volatile("cp.async.wait_group 0;" ::: "memory")

// ===========================================================================
// Converters — dst selected INSIDE device code
// ===========================================================================
__global__ __launch_bounds__(256) void conv_x_kernel(
    const float* __restrict__ src, size_t n)
{
    __half* __restrict__ dst = g_Xh;          // device symbol -> HBM
    for (size_t i = (size_t)blockIdx.x * blockDim.x + threadIdx.x; i < n;
         i += (size_t)gridDim.x * blockDim.x)
        dst[i] = __float2half(src[i]);
}

// W [k=1024][n=cols] fp32 -> WT [n][k=1024] fp16 (dst: 0 -> g_WqkvT, 1 -> g_WoutT)
__global__ __launch_bounds__(256) void convT_kernel(
    const float* __restrict__ W, int cols, int which)
{
    __half* __restrict__ WT = (which == 0) ? g_WqkvT : g_WoutT;
    __shared__ float s[32][33];
    const int n0 = blockIdx.x * 32, k0 = blockIdx.y * 32;
    const int tx = threadIdx.x & 31, ty = threadIdx.x >> 5;   // 32 x 8
    #pragma unroll
    for (int r = 0; r < 32; r += 8)
        s[ty + r][tx] = W[(size_t)(k0 + ty + r) * cols + n0 + tx];
    __syncthreads();
    #pragma unroll
    for (int r = 0; r < 32; r += 8)
        WT[(size_t)(n0 + ty + r) * NC + k0 + tx] = __float2half(s[tx][ty + r]);
}

// ===========================================================================
// fp16 mma GEMM core (proven): block 128x128, BK=64 halves, 3-stage cp.async,
// 256 threads (8 warps 4m x 2n), warp tile 32x64, SW128 + ldmatrix.
// QKV variant: A=g_Xh, BT=g_WqkvT (device symbols), scatter -> f16 Q/K/V.
// ===========================================================================
#define FSTG_BYTES 32768                      // A 16K + B 16K
#define GEMM16_SMEM (3 * FSTG_BYTES)
#define SWC(c, lg) ((uint32_t)(((c) ^ (lg)) << 4))

__global__ __launch_bounds__(256) void gemm_f16_qkv()
{
    const __half* __restrict__ A  = g_Xh;     // device symbols
    const __half* __restrict__ BT = g_WqkvT;

    extern __shared__ char smc[];
    const uint32_t sb = smem_to_u32(smc);

    const int tid  = threadIdx.x;
    const int lane = tid & 31, wid = tid >> 5;
    const int wm = (wid & 3) * 32, wn = (wid >> 2) * 64;
    const int g = lane >> 2, q4 = lane & 3;
    const int lg = lane & 7, l8 = (lane >> 3) & 1, l16 = lane >> 4;
    const int rowA0 = blockIdx.y * 128, colB0 = blockIdx.x * 128;

    uint32_t aRow[2], bRow[4];
    #pragma unroll
    for (int i = 0; i < 2; i++) aRow[i] = (wm + i*16 + lg + l8*8) * 128;
    #pragma unroll
    for (int jg = 0; jg < 4; jg++) bRow[jg] = (wn + jg*16 + lg + l16*8) * 128;

    const int ld_row = tid >> 3, ld_c = tid & 7;

    float acc[2][8][4];
    #pragma unroll
    for (int i = 0; i < 2; i++)
        #pragma unroll
        for (int j = 0; j < 8; j++)
            #pragma unroll
            for (int k = 0; k < 4; k++) acc[i][j][k] = 0.f;

    constexpr int NIT = NC / 64;   // 16

    auto issue = [&](int s) {
        const uint32_t bufA = sb + (s % 3) * FSTG_BYTES;
        const uint32_t bufB = bufA + 16384;
        const int k0 = s * 64;
        #pragma unroll
        for (int r = 0; r < 4; r++) {
            int row = ld_row + r * 32;
            CP_ASYNC16(bufA + row*128 + SWC(ld_c, row & 7),
                       &A[(size_t)(rowA0 + row) * NC + k0 + ld_c*8]);
        }
        #pragma unroll
        for (int r = 0; r < 4; r++) {
            int n = ld_row + r * 32;
            CP_ASYNC16(bufB + n*128 + SWC(ld_c, n & 7),
                       &BT[(size_t)(colB0 + n) * NC + k0 + ld_c*8]);
        }
        CP_COMMIT();
    };

    issue(0);
    issue(1);

    for (int s = 0; s < NIT; s++) {
        if (s + 2 < NIT) CP_WAIT1(); else CP_WAIT0();
        __syncthreads();
        if (s + 2 < NIT) issue(s + 2);

        const uint32_t bufA = sb + (s % 3) * FSTG_BYTES;
        const uint32_t bufB = bufA + 16384;

        #pragma unroll
        for (int kc = 0; kc < 4; kc++) {
            uint32_t af[2][4];
            #pragma unroll
            for (int i = 0; i < 2; i++)
                LDSM_X4(af[i][0], af[i][1], af[i][2], af[i][3],
                        bufA + aRow[i] + SWC(2*kc + l16, lg));
            #pragma unroll
            for (int jg = 0; jg < 4; jg++) {
                uint32_t b0, b1, b2, b3;
                LDSM_X4(b0, b1, b2, b3, bufB + bRow[jg] + SWC(2*kc + l8, lg));
                uint32_t bl[2] = {b0, b1}, bh[2] = {b2, b3};
                mma_f16(acc[0][2*jg],   af[0], bl);
                mma_f16(acc[1][2*jg],   af[1], bl);
                mma_f16(acc[0][2*jg+1], af[0], bh);
                mma_f16(acc[1][2*jg+1], af[1], bh);
            }
        }
    }

    // scatter epilogue -> f16 Q/K/V (proven index math)
    #pragma unroll
    for (int i = 0; i < 2; i++) {
        #pragma unroll
        for (int j = 0; j < 8; j++) {
            #pragma unroll
            for (int half = 0; half < 2; half++) {
                int row = rowA0 + wm + i*16 + g + half*8;
                int col = colB0 + wn + j*8 + 2*q4;
                int which = col >> 10, h = (col >> 6) & 15, d = col & 63;
                int bb = row >> 11, t = row & (NT - 1);
                __half* dst = (which == 0) ? g_Qh : (which == 1) ? g_Kh : g_Vh;
                float sc = (which == 0) ? 0.125f : 1.0f;
                *(uint32_t*)&dst[(((size_t)(bb*NH + h) * NT + t) << 6) + d] =
                    h2pack(acc[i][j][half*2] * sc, acc[i][j][half*2+1] * sc);
            }
        }
    }
}

// Out-projection variant: A=g_AOh, BT=g_WoutT (device symbols) -> fp32 C (arg).
__global__ __launch_bounds__(256) void gemm_f16_out(float* __restrict__ C)
{
    const __half* __restrict__ A  = g_AOh;
    const __half* __restrict__ BT = g_WoutT;

    extern __shared__ char smc[];
    const uint32_t sb = smem_to_u32(smc);

    const int tid  = threadIdx.x;
    const int lane = tid & 31, wid = tid >> 5;
    const int wm = (wid & 3) * 32, wn = (wid >> 2) * 64;
    const int g = lane >> 2, q4 = lane & 3;
    const int lg = lane & 7, l8 = (lane >> 3) & 1, l16 = lane >> 4;
    const int rowA0 = blockIdx.y * 128, colB0 = blockIdx.x * 128;

    uint32_t aRow[2], bRow[4];
    #pragma unroll
    for (int i = 0; i < 2; i++) aRow[i] = (wm + i*16 + lg + l8*8) * 128;
    #pragma unroll
    for (int jg = 0; jg < 4; jg++) bRow[jg] = (wn + jg*16 + lg + l16*8) * 128;

    const int ld_row = tid >> 3, ld_c = tid & 7;

    float acc[2][8][4];
    #pragma unroll
    for (int i = 0; i < 2; i++)
        #pragma unroll
        for (int j = 0; j < 8; j++)
            #pragma unroll
            for (int k = 0; k < 4; k++) acc[i][j][k] = 0.f;

    constexpr int NIT = NC / 64;   // 16

    auto issue = [&](int s) {
        const uint32_t bufA = sb + (s % 3) * FSTG_BYTES;
        const uint32_t bufB = bufA + 16384;
        const int k0 = s * 64;
        #pragma unroll
        for (int r = 0; r < 4; r++) {
            int row = ld_row + r * 32;
            CP_ASYNC16(bufA + row*128 + SWC(ld_c, row & 7),
                       &A[(size_t)(rowA0 + row) * NC + k0 + ld_c*8]);
        }
        #pragma unroll
        for (int r = 0; r < 4; r++) {
            int n = ld_row + r * 32;
            CP_ASYNC16(bufB + n*128 + SWC(ld_c, n & 7),
                       &BT[(size_t)(colB0 + n) * NC + k0 + ld_c*8]);
        }
        CP_COMMIT();
    };

    issue(0);
    issue(1);

    for (int s = 0; s < NIT; s++) {
        if (s + 2 < NIT) CP_WAIT1(); else CP_WAIT0();
        __syncthreads();
        if (s + 2 < NIT) issue(s + 2);

        const uint32_t bufA = sb + (s % 3) * FSTG_BYTES;
        const uint32_t bufB = bufA + 16384;

        #pragma unroll
        for (int kc = 0; kc < 4; kc++) {
            uint32_t af[2][4];
            #pragma unroll
            for (int i = 0; i < 2; i++)
                LDSM_X4(af[i][0], af[i][1], af[i][2], af[i][3],
                        bufA + aRow[i] + SWC(2*kc + l16, lg));
            #pragma unroll
            for (int jg = 0; jg < 4; jg++) {
                uint32_t b0, b1, b2, b3;
                LDSM_X4(b0, b1, b2, b3, bufB + bRow[jg] + SWC(2*kc + l8, lg));
                uint32_t bl[2] = {b0, b1}, bh[2] = {b2, b3};
                mma_f16(acc[0][2*jg],   af[0], bl);
                mma_f16(acc[1][2*jg],   af[1], bl);
                mma_f16(acc[0][2*jg+1], af[0], bh);
                mma_f16(acc[1][2*jg+1], af[1], bh);
            }
        }
    }

    #pragma unroll
    for (int i = 0; i < 2; i++) {
        #pragma unroll
        for (int j = 0; j < 8; j++) {
            #pragma unroll
            for (int half = 0; half < 2; half++) {
                int row = rowA0 + wm + i*16 + g + half*8;
                int col = colB0 + wn + j*8 + 2*q4;
                *(float2*)&C[(size_t)row * NC + col] =
                    make_float2(acc[i][j][half*2], acc[i][j][half*2+1]);
            }
        }
    }
}

// ===========================================================================
// PROVEN fp16 flash attention; writes fp16 g_AOh via device symbol.
// ===========================================================================
#define ATTN_SMEM (8192 + 2*16384)

__global__ __launch_bounds__(128) void attn_f16()
{
    extern __shared__ char smc[];
    const uint32_t sb = smem_to_u32(smc);

    const int tid = threadIdx.x;
    const int lane = tid & 31, w = tid >> 5;
    const int g = lane >> 2, q4 = lane & 3;
    const int lg = lane & 7, l8 = (lane >> 3) & 1, l16 = lane >> 4;
    const int qt = blockIdx.x, bh = blockIdx.y;
    const int b = bh >> 4, h = bh & 15;
    const int q0 = qt * 64;

    const __half* Qg  = g_Qh + ((size_t)bh * NT + q0) * ND;
    const __half* Kg0 = g_Kh + (size_t)bh * NT * ND;
    const __half* Vg0 = g_Vh + (size_t)bh * NT * ND;

    const int ld_row = tid >> 3, ld_c = tid & 7;

    #pragma unroll
    for (int r = 0; r < 4; r++) {
        int row = ld_row + r * 16;
        CP_ASYNC16(sb + row*128 + SWC(ld_c, row & 7), &Qg[row*ND + ld_c*8]);
    }
    CP_COMMIT();
    CP_WAIT0();
    __syncthreads();

    uint32_t qf[4][4];
    {
        uint32_t qRow = sb + (w*16 + lg + l8*8) * 128;
        #pragma unroll
        for (int kc = 0; kc < 4; kc++)
            LDSM_X4(qf[kc][0], qf[kc][1], qf[kc][2], qf[kc][3],
                    qRow + SWC(2*kc + l16, lg));
    }
    __syncthreads();

    uint32_t kRow[4], vRow[4];
    #pragma unroll
    for (int ng = 0; ng < 4; ng++) kRow[ng] = (ng*16 + lg + l16*8) * 128;
    #pragma unroll
    for (int kc = 0; kc < 4; kc++) vRow[kc] = (kc*16 + lg + l8*8) * 128;

    auto issueKV = [&](int jt) {
        const uint32_t kb = sb + 8192 + (jt & 1) * 16384;
        const uint32_t vb = kb + 8192;
        const __half* Kg = Kg0 + (size_t)jt*64*ND;
        const __half* Vg = Vg0 + (size_t)jt*64*ND;
        #pragma unroll
        for (int r = 0; r < 4; r++) {
            int row = ld_row + r * 16;
            uint32_t swo = row*128 + SWC(ld_c, row & 7);
            CP_ASYNC16(kb + swo, &Kg[row*ND + ld_c*8]);
            CP_ASYNC16(vb + swo, &Vg[row*ND + ld_c*8]);
        }
        CP_COMMIT();
    };

    float o[8][4];
    #pragma unroll
    for (int i = 0; i < 8; i++)
        #pragma unroll
        for (int j = 0; j < 4; j++) o[i][j] = 0.f;
    float m0 = -1e30f, m1 = -1e30f, l0 = 0.f, l1 = 0.f;

    issueKV(0);

    for (int jt = 0; jt <= qt; jt++) {
        __syncthreads();
        if (jt + 1 <= qt) { issueKV(jt + 1); CP_WAIT1(); }
        else              { CP_WAIT0(); }
        __syncthreads();

        const uint32_t kb = sb + 8192 + (jt & 1) * 16384;
        const uint32_t vb = kb + 8192;

        float s[8][4];
        #pragma unroll
        for (int i = 0; i < 8; i++)
            #pragma unroll
            for (int j = 0; j < 4; j++) s[i][j] = 0.f;
        #pragma unroll
        for (int kc = 0; kc < 4; kc++) {
            #pragma unroll
            for (int ng = 0; ng < 4; ng++) {
                uint32_t b0, b1, b2, b3;
                LDSM_X4(b0, b1, b2, b3, kb + kRow[ng] + SWC(2*kc + l8, lg));
                uint32_t bl[2] = {b0, b1}, bhh[2] = {b2, b3};
                mma_f16(s[2*ng],   qf[kc], bl);
                mma_f16(s[2*ng+1], qf[kc], bhh);
            }
        }

        if (jt == qt) {
            int r0 = w*16 + g, r1 = r0 + 8;
            #pragma unroll
            for (int nf = 0; nf < 8; nf++) {
                int c = nf*8 + 2*q4;
                if (c     > r0) s[nf][0] = -1e30f;
                if (c + 1 > r0) s[nf][1] = -1e30f;
                if (c     > r1) s[nf][2] = -1e30f;
                if (c + 1 > r1) s[nf][3] = -1e30f;
            }
        }

        float mx0 = -1e30f, mx1 = -1e30f;
        #pragma unroll
        for (int nf = 0; nf < 8; nf++) {
            mx0 = fmaxf(mx0, fmaxf(s[nf][0], s[nf][1]));
            mx1 = fmaxf(mx1, fmaxf(s[nf][2], s[nf][3]));
        }
        mx0 = fmaxf(mx0, __shfl_xor_sync(0xffffffffu, mx0, 1));
        mx0 = fmaxf(mx0, __shfl_xor_sync(0xffffffffu, mx0, 2));
        mx1 = fmaxf(mx1, __shfl_xor_sync(0xffffffffu, mx1, 1));
        mx1 = fmaxf(mx1, __shfl_xor_sync(0xffffffffu, mx1, 2));
        float nm0 = fmaxf(m0, mx0), nm1 = fmaxf(m1, mx1);
        float c0 = __expf(m0 - nm0), c1 = __expf(m1 - nm1);
        m0 = nm0; m1 = nm1;
        float ps0 = 0.f, ps1 = 0.f;
        #pragma unroll
        for (int nf = 0; nf < 8; nf++) {
            s[nf][0] = __expf(s[nf][0] - nm0);
            s[nf][1] = __expf(s[nf][1] - nm0);
            s[nf][2] = __expf(s[nf][2] - nm1);
            s[nf][3] = __expf(s[nf][3] - nm1);
            ps0 += s[nf][0] + s[nf][1];
            ps1 += s[nf][2] + s[nf][3];
        }
        ps0 += __shfl_xor_sync(0xffffffffu, ps0, 1);
        ps0 += __shfl_xor_sync(0xffffffffu, ps0, 2);
        ps1 += __shfl_xor_sync(0xffffffffu, ps1, 1);
        ps1 += __shfl_xor_sync(0xffffffffu, ps1, 2);
        l0 = l0 * c0 + ps0;
        l1 = l1 * c1 + ps1;
        #pragma unroll
        for (int df = 0; df < 8; df++) {
            o[df][0] *= c0; o[df][1] *= c0;
            o[df][2] *= c1; o[df][3] *= c1;
        }

        uint32_t p[4][4];
        #pragma unroll
        for (int kc = 0; kc < 4; kc++) {
            p[kc][0] = h2pack(s[2*kc][0],   s[2*kc][1]);
            p[kc][1] = h2pack(s[2*kc][2],   s[2*kc][3]);
            p[kc][2] = h2pack(s[2*kc+1][0], s[2*kc+1][1]);
            p[kc][3] = h2pack(s[2*kc+1][2], s[2*kc+1][3]);
        }

        #pragma unroll
        for (int kc = 0; kc < 4; kc++) {
            #pragma unroll
            for (int dg = 0; dg < 4; dg++) {
                uint32_t v0, v1, v2, v3;
                LDSM_X4_T(v0, v1, v2, v3, vb + vRow[kc] + SWC(2*dg + l16, lg));
                uint32_t bl[2] = {v0, v1}, bhh[2] = {v2, v3};
                mma_f16(o[2*dg],   p[kc], bl);
                mma_f16(o[2*dg+1], p[kc], bhh);
            }
        }
    }

    // normalize, write fp16 to g_AOh (device symbol)
    float i0 = 1.f / l0, i1 = 1.f / l1;
    int r0 = q0 + w*16 + g;
    #pragma unroll
    for (int df = 0; df < 8; df++) {
        int col = h*ND + df*8 + 2*q4;
        *(uint32_t*)&g_AOh[(size_t)(b*NT + r0) * NC + col] =
            h2pack(o[df][0]*i0, o[df][1]*i0);
        *(uint32_t*)&g_AOh[(size_t)(b*NT + r0 + 8) * NC + col] =
            h2pack(o[df][2]*i1, o[df][3]*i1);
    }
}

// ---------------------------------------------------------------------------
extern "C" void kernel_launch(void* const* d_in, const int* in_sizes, int n_in,
                              void* d_out, int out_size)
{
    const float* x    = (const float*)d_in[0];
    const float* Wqkv = (const float*)d_in[1];
    const float* Wout = (const float*)d_in[2];
    // mask is deterministic tril -> hard-coded causal
    float* out = (float*)d_out;

    cudaFuncSetAttribute(gemm_f16_qkv,
                         cudaFuncAttributeMaxDynamicSharedMemorySize, GEMM16_SMEM);
    cudaFuncSetAttribute(gemm_f16_out,
                         cudaFuncAttributeMaxDynamicSharedMemorySize, GEMM16_SMEM);
    cudaFuncSetAttribute(attn_f16,
                         cudaFuncAttributeMaxDynamicSharedMemorySize, ATTN_SMEM);

    // converts (dst selected in device code)
    conv_x_kernel<<<2048, 256>>>(x, (size_t)NM * NC);
    convT_kernel<<<dim3(3*NC/32, NC/32), 256>>>(Wqkv, 3*NC, 0);
    convT_kernel<<<dim3(NC/32, NC/32), 256>>>(Wout, NC, 1);

    dim3 g1(3*NC / 128, NM / 128);   // 24 x 64
    gemm_f16_qkv<<<g1, 256, GEMM16_SMEM>>>();

    dim3 ga(NT / 64, NB * NH);       // 32 x 64
    attn_f16<<<ga, 128, ATTN_SMEM>>>();

    dim3 g2(NC / 128, NM / 128);     // 8 x 64
    gemm_f16_out<<<g2, 256, GEMM16_SMEM>>>(out);
}